// round 13
// baseline (speedup 1.0000x reference)
#include <cuda_runtime.h>
#include <cuda_fp16.h>
#include <mma.h>
#include <math.h>
#include <stdint.h>

using namespace nvcuda;

// Problem constants: B=16, N=1024, C=768, H=12, HD=64, one mini-batch (m=1024)
#define NTOK   16384
#define CDIM   768
#define NHEAD  12
#define HD     64
#define BH     192
#define TOKHD  65536          // 1024*64 per (b,h)

// ---- scratch (static device globals; no allocations anywhere) ----
__device__ float  g_eta[196608];     // [B,H,N]
__device__ float  g_b1part[98304];   // [BH,8,64] partial b1 grad sums
__device__ float  g_W1part[6291456]; // [BH,8,64,64] partial W1 grads
__device__ __half g_Xh[12582912];    // half(x) [16384,768]
__device__ __half g_Wqh[1769472];    // half(qkv_weight) [2304,768]
__device__ __half g_Wph[589824];     // half(proj_weight) [768,768]
__device__ __half g_XQWh[12582912];  // half pre-projection [B,N,C]
__device__ __half g_Qh[12582912];    // half Q [B,H,N,64]
__device__ __half g_Kh[12582912];    // half K
__device__ __half g_Vh[12582912];    // half V
__device__ __half g_Gh[12582912];    // half g scaled by 1024

__device__ __forceinline__ float warp_sum(float v) {
#pragma unroll
    for (int o = 16; o > 0; o >>= 1) v += __shfl_xor_sync(0xffffffffu, v, o);
    return v;
}
__device__ __forceinline__ void warp_sum2(float& a, float& b) {
#pragma unroll
    for (int o = 16; o > 0; o >>= 1) {
        a += __shfl_xor_sync(0xffffffffu, a, o);
        b += __shfl_xor_sync(0xffffffffu, b, o);
    }
}
__device__ __forceinline__ uint32_t smem_u32(const void* p) {
    uint32_t a;
    asm("{ .reg .u64 t; cvta.to.shared.u64 t, %1; cvt.u32.u64 %0, t; }"
        : "=r"(a) : "l"(p));
    return a;
}
__device__ __forceinline__ void cp16(uint32_t dst, const void* src) {
    asm volatile("cp.async.cg.shared.global [%0], [%1], 16;" :: "r"(dst), "l"(src));
}
__device__ __forceinline__ void cp_commit() {
    asm volatile("cp.async.commit_group;" ::: "memory");
}
template <int N> __device__ __forceinline__ void cp_wait() {
    asm volatile("cp.async.wait_group %0;" :: "n"(N) : "memory");
}

// ============================================================
// dual fp32 -> fp16 conversion (both weight matrices, one launch)
// ============================================================
__global__ void f2h_dual(const float* __restrict__ a, __half* __restrict__ oa, int na2,
                         const float* __restrict__ b, __half* __restrict__ ob, int nb2)
{
    int i = blockIdx.x * blockDim.x + threadIdx.x;
    if (i < na2) {
        float2 v = ((const float2*)a)[i];
        ((__half2*)oa)[i] = __floats2half2_rn(v.x, v.y);
    } else if (i - na2 < nb2) {
        int j = i - na2;
        float2 v = ((const float2*)b)[j];
        ((__half2*)ob)[j] = __floats2half2_rn(v.x, v.y);
    }
}

// ============================================================
// fp16 wmma GEMM (round-10 proven config, FROZEN):
// Tile 128x128, 256 threads, 8 warps (warp tile 64x32),
// K chunks of 32, 3-stage cp.async pipeline, 2 CTAs/SM.
// MODE 0: half-only Q/K/V out; MODE 1: fp32 out.
// ============================================================
#define KCH 32
#define KPAD 40
#define BUF_HALFS (128 * KPAD)
#define NSTAGE 3
#define GEMM_SMEM (NSTAGE * 2 * BUF_HALFS * 2)

template <int MODE>
__global__ __launch_bounds__(256, 2) void gemm_fp16(
    const __half* __restrict__ A, const __half* __restrict__ Bw,
    const float* __restrict__ bias0, const float* __restrict__ bias1,
    float* __restrict__ outp)
{
    extern __shared__ __half hsm[];
    __shared__ union {
        float bias2d[16][132];
        float stg[8][16 * 18];
    } u;

    int t = threadIdx.x;
    int w = t >> 5, lid = t & 31;
    int wy = w >> 2, wx = w & 3;
    int m0 = blockIdx.y * 128, n0 = blockIdx.x * 128;

    if (t < 128) {
        int col = n0 + t;
        float bv;
        if (MODE == 0) {
            int which = col / 768, c = col - which * 768;
            bv = (which == 0) ? bias0[c] : ((which == 2) ? bias1[c] : 0.f);
        } else bv = bias0[col];
#pragma unroll
        for (int r = 0; r < 16; r++) u.bias2d[r][t] = bv;
    }
    __syncthreads();

    wmma::fragment<wmma::accumulator, 16, 16, 16, float> acc[4][2];
#pragma unroll
    for (int i = 0; i < 4; i++)
#pragma unroll
        for (int j = 0; j < 2; j++)
            wmma::load_matrix_sync(acc[i][j], &u.bias2d[0][wx * 32 + j * 16], 132,
                                   wmma::mem_row_major);
    __syncthreads();

    const __half* gA = A + (size_t)m0 * 768;
    const __half* gB = Bw + (size_t)n0 * 768;

    auto stA = [&](int s) -> __half* { return hsm + s * 2 * BUF_HALFS; };
    auto stB = [&](int s) -> __half* { return hsm + s * 2 * BUF_HALFS + BUF_HALFS; };

    auto load_chunk = [&](int kc, int s) {
        uint32_t aS = smem_u32(stA(s));
        uint32_t bS = smem_u32(stB(s));
#pragma unroll
        for (int j = 0; j < 2; j++) {
            int idx = t + j * 256;
            int row = idx >> 2, c4 = idx & 3;
            cp16(aS + row * (KPAD * 2) + c4 * 16,
                 gA + (size_t)row * 768 + kc * KCH + c4 * 8);
            cp16(bS + row * (KPAD * 2) + c4 * 16,
                 gB + (size_t)row * 768 + kc * KCH + c4 * 8);
        }
        cp_commit();
    };

    const int NCHUNK = 24;
    load_chunk(0, 0);
    load_chunk(1, 1);
    for (int i = 0; i < NCHUNK; i++) {
        int s = i % NSTAGE;
        if (i + 2 < NCHUNK) { load_chunk(i + 2, (i + 2) % NSTAGE); cp_wait<2>(); }
        else if (i + 1 < NCHUNK) cp_wait<1>();
        else cp_wait<0>();
        __syncthreads();

        __half* As = stA(s);
        __half* Bs = stB(s);
#pragma unroll
        for (int kk = 0; kk < KCH; kk += 16) {
            wmma::fragment<wmma::matrix_a, 16, 16, 16, __half, wmma::row_major> af[4];
            wmma::fragment<wmma::matrix_b, 16, 16, 16, __half, wmma::col_major> bf[2];
#pragma unroll
            for (int q = 0; q < 4; q++)
                wmma::load_matrix_sync(af[q], &As[(wy * 64 + q * 16) * KPAD + kk], KPAD);
#pragma unroll
            for (int q = 0; q < 2; q++)
                wmma::load_matrix_sync(bf[q], &Bs[(wx * 32 + q * 16) * KPAD + kk], KPAD);
#pragma unroll
            for (int q = 0; q < 4; q++)
#pragma unroll
                for (int r = 0; r < 2; r++)
                    wmma::mma_sync(acc[q][r], af[q], bf[r], acc[q][r]);
        }
        __syncthreads();
    }

#pragma unroll
    for (int i = 0; i < 4; i++) {
        int row0 = m0 + wy * 64 + i * 16;
#pragma unroll
        for (int j = 0; j < 2; j++) {
            int col0 = n0 + wx * 32 + j * 16;
            if (MODE == 0) {
                int b = row0 >> 10, n = row0 & 1023;
                int which = col0 / 768;
                int c = col0 - which * 768;
                int h = c >> 6, d0 = c & 63;
                size_t off = ((size_t)(b * NHEAD + h) << 16) + (n << 6) + d0;
                __half* dsth = (which == 0 ? g_Qh : (which == 1 ? g_Kh : g_Vh)) + off;
                float* stw = &u.stg[w][0];
                wmma::store_matrix_sync(stw, acc[i][j], 18, wmma::mem_row_major);
                __syncwarp();
                int rr = lid >> 1, cc = (lid & 1) * 8;
                float* sp = stw + rr * 18 + cc;
                __half2 h0 = __floats2half2_rn(sp[0], sp[1]);
                __half2 h1 = __floats2half2_rn(sp[2], sp[3]);
                __half2 h2 = __floats2half2_rn(sp[4], sp[5]);
                __half2 h3 = __floats2half2_rn(sp[6], sp[7]);
                __half2* dp = (__half2*)(dsth + (size_t)rr * 64 + cc);
                dp[0] = h0; dp[1] = h1; dp[2] = h2; dp[3] = h3;
                __syncwarp();
            } else {
                wmma::store_matrix_sync(outp + (size_t)row0 * 768 + col0, acc[i][j],
                                        768, wmma::mem_row_major);
            }
        }
    }
}

// ============================================================
// learned LR + fused f2h(x). 512 blocks x 32 rows, paired reductions.
// ============================================================
__global__ __launch_bounds__(256) void lr_kernel2(
    const float* __restrict__ x, const float* __restrict__ lrw,
    const float* __restrict__ lrb, __half* __restrict__ Xh)
{
    __shared__ float ws[12 * 768];
    __shared__ float lb[12];
    int t = threadIdx.x, w = t >> 5, l = t & 31;
    for (int i = t; i < 12 * 768; i += 256) ws[i] = lrw[i];
    if (t < 12) lb[t] = lrb[t];
    __syncthreads();

    int rowbase = blockIdx.x * 32 + w * 4;
    for (int rr = 0; rr < 4; rr++) {
        int row = rowbase + rr;
        const float* xr = x + (size_t)row * 768;
        float xv[24];
#pragma unroll
        for (int k = 0; k < 24; k++) xv[k] = xr[l + k * 32];
        __half* xo = Xh + (size_t)row * 768;
#pragma unroll
        for (int k = 0; k < 24; k++) xo[l + k * 32] = __float2half(xv[k]);
        int b = row >> 10, n = row & 1023;
#pragma unroll
        for (int h = 0; h < 12; h += 2) {
            float s0 = 0.f, s1 = 0.f;
#pragma unroll
            for (int k = 0; k < 24; k++) {
                s0 = fmaf(xv[k], ws[h * 768 + l + k * 32], s0);
                s1 = fmaf(xv[k], ws[(h + 1) * 768 + l + k * 32], s1);
            }
            warp_sum2(s0, s1);
            if (l == 0) {
                float v0 = 1.f / (1.f + expf(-(s0 + lb[h])));
                float v1 = 1.f / (1.f + expf(-(s1 + lb[h + 1])));
                g_eta[(b * NHEAD + h) * 1024 + n]     = v0 * (1.f / 64.f);
                g_eta[(b * NHEAD + h + 1) * 1024 + n] = v1 * (1.f / 64.f);
            }
        }
    }
}

// ============================================================
// phase1 (tensor cores, 8-way split) + fused gradw partial.
// block = (bh, part8): 128 rows. One wmma block + 16 LN rows per warp,
// then 128-deep XK^T @ g partial -> g_W1part[bh][part8].
// ============================================================
__global__ __launch_bounds__(256) void ttt_phase1_tc(
    const float* __restrict__ W1, const float* __restrict__ b1,
    const float* __restrict__ gamma, const float* __restrict__ beta)
{
    int bh = blockIdx.x >> 3, part = blockIdx.x & 7;
    int h = bh % NHEAD;
    __shared__ __half W1h[64 * 72];
    __shared__ float zs[8][16 * 68];
    __shared__ float b1s[64], gs[64], bs[64];
    __shared__ float gbacc[8 * 64];
    int t = threadIdx.x, w = t >> 5, l = t & 31;

    for (int i = t; i < 4096; i += 256) {
        int r = i >> 6, c = i & 63;
        W1h[r * 72 + c] = __float2half(W1[h * 4096 + i]);
    }
    if (t < 64) {
        b1s[t] = b1[h * 64 + t];
        gs[t]  = gamma[h * 64 + t];
        bs[t]  = beta[h * 64 + t];
    }
    __syncthreads();

    const __half* Kh = g_Kh + (size_t)bh * TOKHD;
    const __half* Vh = g_Vh + (size_t)bh * TOKHD;
    __half* Gh = g_Gh + (size_t)bh * TOKHD;
    const float* etap = g_eta + bh * 1024;

    int row0 = part * 128 + w * 16;
    {
        wmma::fragment<wmma::accumulator, 16, 16, 16, float> acc[4];
#pragma unroll
        for (int n = 0; n < 4; n++) wmma::fill_fragment(acc[n], 0.f);
#pragma unroll
        for (int k = 0; k < 4; k++) {
            wmma::fragment<wmma::matrix_a, 16, 16, 16, __half, wmma::row_major> af;
            wmma::load_matrix_sync(af, Kh + (size_t)row0 * 64 + k * 16, 64);
#pragma unroll
            for (int n = 0; n < 4; n++) {
                wmma::fragment<wmma::matrix_b, 16, 16, 16, __half, wmma::row_major> bf;
                wmma::load_matrix_sync(bf, &W1h[(k * 16) * 72 + n * 16], 72);
                wmma::mma_sync(acc[n], af, bf, acc[n]);
            }
        }
#pragma unroll
        for (int n = 0; n < 4; n++)
            wmma::store_matrix_sync(&zs[w][n * 16], acc[n], 68, wmma::mem_row_major);
        __syncwarp();
    }

    float gb0 = 0.f, gb1 = 0.f;
#pragma unroll
    for (int r = 0; r < 16; r++) {
        int row = row0 + r;
        float z0 = zs[w][r * 68 + l] + b1s[l];
        float z1 = zs[w][r * 68 + l + 32] + b1s[l + 32];
        float s1 = z0 + z1, s2 = z0 * z0 + z1 * z1;
        warp_sum2(s1, s2);
        float mu = s1 * (1.f / 64.f);
        float var = s2 * (1.f / 64.f) - mu * mu;
        float rstd = rsqrtf(var + 1e-6f);
        float xh0 = (z0 - mu) * rstd, xh1 = (z1 - mu) * rstd;
        float xk0 = __half2float(Kh[row * 64 + l]);
        float xk1 = __half2float(Kh[row * 64 + l + 32]);
        float xv0 = __half2float(Vh[row * 64 + l]);
        float xv1 = __half2float(Vh[row * 64 + l + 32]);
        float go0 = gs[l] * xh0 + bs[l] - (xv0 - xk0);
        float go1 = gs[l + 32] * xh1 + bs[l + 32] - (xv1 - xk1);
        float gg0 = go0 * gs[l], gg1 = go1 * gs[l + 32];
        float sg = gg0 + gg1, sgx = gg0 * xh0 + gg1 * xh1;
        warp_sum2(sg, sgx);
        float sc = etap[row] * rstd * (1.f / 64.f) * (1.f / 1024.f);
        float gf0 = (64.f * gg0 - sg - xh0 * sgx) * sc;
        float gf1 = (64.f * gg1 - sg - xh1 * sgx) * sc;
        Gh[row * 64 + l]      = __float2half(gf0 * 1024.f);
        Gh[row * 64 + l + 32] = __float2half(gf1 * 1024.f);
        gb0 += gf0; gb1 += gf1;
    }
    gbacc[w * 64 + l] = gb0;
    gbacc[w * 64 + l + 32] = gb1;
    __syncthreads();   // all 128 rows of Gh written + gbacc ready
    if (t < 64) {
        float s = 0.f;
#pragma unroll
        for (int ww = 0; ww < 8; ww++) s += gbacc[ww * 64 + t];
        g_b1part[(bh * 8 + part) * 64 + t] = s;
    }

    // fused gradw partial: XK[part]^T @ g[part], 128 rows deep
    {
        const __half* Kp2 = Kh + part * 128 * 64;
        const __half* Gp2 = Gh + part * 128 * 64;
        int wt = w & 3, kh2 = w >> 2;
        wmma::fragment<wmma::accumulator, 16, 16, 16, float> acc2[4];
#pragma unroll
        for (int n = 0; n < 4; n++) wmma::fill_fragment(acc2[n], 0.f);
#pragma unroll
        for (int ks = 0; ks < 4; ks++) {
            int k = kh2 * 64 + ks * 16;
            wmma::fragment<wmma::matrix_a, 16, 16, 16, __half, wmma::col_major> af;
            wmma::load_matrix_sync(af, Kp2 + (size_t)k * 64 + wt * 16, 64);
#pragma unroll
            for (int n = 0; n < 4; n++) {
                wmma::fragment<wmma::matrix_b, 16, 16, 16, __half, wmma::row_major> bf;
                wmma::load_matrix_sync(bf, Gp2 + (size_t)k * 64 + n * 16, 64);
                wmma::mma_sync(acc2[n], af, bf, acc2[n]);
            }
        }
        __syncthreads();   // zs free for reuse
#pragma unroll
        for (int n = 0; n < 4; n++)
            wmma::store_matrix_sync(&zs[w][n * 16], acc2[n], 68, wmma::mem_row_major);
        __syncthreads();

        float* dst = g_W1part + (size_t)(bh * 8 + part) * 4096;
        for (int i = t; i < 4096; i += 256) {
            int d = i >> 6, e = i & 63;
            int wt2 = d >> 4, r = d & 15;
            dst[i] = zs[wt2][r * 68 + e] + zs[wt2 + 4][r * 68 + e];
        }
    }
}

// ============================================================
// phase3 (tensor cores, 4-way split) with fused 8-partial combine:
// W1h = half(W1 - sum_8(W1part)/1024), b1s = b1 - sum_8(b1part),
// then Z = XQ_h @ W1h + b1s, fp32 LN fwd, out -> g_XQWh.
// ============================================================
__global__ __launch_bounds__(256) void ttt_phase3_tc(
    const float* __restrict__ W1, const float* __restrict__ b1,
    const float* __restrict__ gamma, const float* __restrict__ beta)
{
    int bh = blockIdx.x >> 2, part = blockIdx.x & 3;
    int h = bh % NHEAD, b = bh / NHEAD;
    __shared__ __half W1h[64 * 72];
    __shared__ float zs[8][16 * 68];
    __shared__ float b1s[64], gs[64], bs[64];
    int t = threadIdx.x, w = t >> 5, l = t & 31;

    {   // fused combine: fold 8 fp32 partials into half W1h
        const float* pb8 = g_W1part + (size_t)(bh * 8) * 4096;
        for (int i = t; i < 4096; i += 256) {
            int r = i >> 6, c = i & 63;
            float s = 0.f;
#pragma unroll
            for (int j = 0; j < 8; j++) s += pb8[(size_t)j * 4096 + i];
            W1h[r * 72 + c] = __float2half(W1[h * 4096 + i] - s * (1.f / 1024.f));
        }
    }
    if (t < 64) {
        float s = 0.f;
#pragma unroll
        for (int j = 0; j < 8; j++) s += g_b1part[(bh * 8 + j) * 64 + t];
        b1s[t] = b1[h * 64 + t] - s;
        gs[t]  = gamma[h * 64 + t];
        bs[t]  = beta[h * 64 + t];
    }
    __syncthreads();

    const __half* Qh = g_Qh + (size_t)bh * TOKHD;
    __half* Op = g_XQWh + (size_t)b * 1024 * CDIM;

    for (int s = 0; s < 2; s++) {
        int row0 = part * 256 + (s * 8 + w) * 16;
        wmma::fragment<wmma::accumulator, 16, 16, 16, float> acc[4];
#pragma unroll
        for (int n = 0; n < 4; n++) wmma::fill_fragment(acc[n], 0.f);
#pragma unroll
        for (int k = 0; k < 4; k++) {
            wmma::fragment<wmma::matrix_a, 16, 16, 16, __half, wmma::row_major> af;
            wmma::load_matrix_sync(af, Qh + (size_t)row0 * 64 + k * 16, 64);
#pragma unroll
            for (int n = 0; n < 4; n++) {
                wmma::fragment<wmma::matrix_b, 16, 16, 16, __half, wmma::row_major> bf;
                wmma::load_matrix_sync(bf, &W1h[(k * 16) * 72 + n * 16], 72);
                wmma::mma_sync(acc[n], af, bf, acc[n]);
            }
        }
#pragma unroll
        for (int n = 0; n < 4; n++)
            wmma::store_matrix_sync(&zs[w][n * 16], acc[n], 68, wmma::mem_row_major);
        __syncwarp();

#pragma unroll
        for (int r = 0; r < 16; r++) {
            int row = row0 + r;
            float z0 = zs[w][r * 68 + l] + b1s[l];
            float z1 = zs[w][r * 68 + l + 32] + b1s[l + 32];
            float s1 = z0 + z1, s2 = z0 * z0 + z1 * z1;
            warp_sum2(s1, s2);
            float mu = s1 * (1.f / 64.f);
            float var = s2 * (1.f / 64.f) - mu * mu;
            float rstd = rsqrtf(var + 1e-6f);
            float y0 = gs[l] * ((z0 - mu) * rstd) + bs[l];
            float y1 = gs[l + 32] * ((z1 - mu) * rstd) + bs[l + 32];
            float xq0 = __half2float(Qh[row * 64 + l]);
            float xq1 = __half2float(Qh[row * 64 + l + 32]);
            Op[row * CDIM + h * 64 + l]      = __float2half(xq0 + y0);
            Op[row * CDIM + h * 64 + l + 32] = __float2half(xq1 + y1);
        }
    }
}

// ============================================================
extern "C" void kernel_launch(void* const* d_in, const int* in_sizes, int n_in,
                              void* d_out, int out_size)
{
    (void)in_sizes; (void)n_in; (void)out_size;
    const float* x     = (const float*)d_in[0];
    const float* qkvw  = (const float*)d_in[1];
    const float* qb    = (const float*)d_in[2];
    const float* vb    = (const float*)d_in[3];
    const float* pw    = (const float*)d_in[4];
    const float* pb    = (const float*)d_in[5];
    const float* lrw   = (const float*)d_in[6];
    const float* lrb   = (const float*)d_in[7];
    const float* gamma = (const float*)d_in[8];
    const float* beta  = (const float*)d_in[9];
    const float* W1    = (const float*)d_in[10];
    const float* b1    = (const float*)d_in[11];
    float* out = (float*)d_out;

    cudaFuncSetAttribute(gemm_fp16<0>, cudaFuncAttributeMaxDynamicSharedMemorySize, GEMM_SMEM);
    cudaFuncSetAttribute(gemm_fp16<1>, cudaFuncAttributeMaxDynamicSharedMemorySize, GEMM_SMEM);

    __half *Xh, *Wqh, *Wph, *XQWh;
    cudaGetSymbolAddress((void**)&Xh, g_Xh);
    cudaGetSymbolAddress((void**)&Wqh, g_Wqh);
    cudaGetSymbolAddress((void**)&Wph, g_Wph);
    cudaGetSymbolAddress((void**)&XQWh, g_XQWh);

    lr_kernel2<<<512, 256>>>(x, lrw, lrb, Xh);
    f2h_dual<<<(884736 + 294912 + 255) / 256, 256>>>(qkvw, Wqh, 884736,
                                                     pw, Wph, 294912);

    gemm_fp16<0><<<dim3(18, 128), 256, GEMM_SMEM>>>(Xh, Wqh, qb, vb, nullptr);

    ttt_phase1_tc<<<1536, 256>>>(W1, b1, gamma, beta);
    ttt_phase3_tc<<<768, 256>>>(W1, b1, gamma, beta);

    gemm_fp16<1><<<dim3(6, 128), 256, GEMM_SMEM>>>(XQWh, Wph, pb, nullptr, out);
}

// round 14
// speedup vs baseline: 1.0433x; 1.0433x over previous
#include <cuda_runtime.h>
#include <cuda_fp16.h>
#include <mma.h>
#include <math.h>
#include <stdint.h>

using namespace nvcuda;

// Problem constants: B=16, N=1024, C=768, H=12, HD=64, one mini-batch (m=1024)
#define NTOK   16384
#define CDIM   768
#define NHEAD  12
#define HD     64
#define BH     192
#define TOKHD  65536          // 1024*64 per (b,h)

// ---- scratch (static device globals; no allocations anywhere) ----
__device__ float  g_eta[196608];     // [B,H,N]
__device__ float  g_b1part[49152];   // [BH,4,64] partial b1 grad sums
__device__ float  g_W1part[3145728]; // [BH,4,64,64] partial W1 grads
__device__ __half g_Xh[12582912];    // half(x) [16384,768]
__device__ __half g_Wqh[1769472];    // half(qkv_weight) [2304,768]
__device__ __half g_Wph[589824];     // half(proj_weight) [768,768]
__device__ __half g_XQWh[12582912];  // half pre-projection [B,N,C]
__device__ __half g_Qh[12582912];    // half Q [B,H,N,64]
__device__ __half g_Kh[12582912];    // half K
__device__ __half g_Vh[12582912];    // half V
__device__ __half g_Gh[12582912];    // half g scaled by 1024

__device__ __forceinline__ float warp_sum(float v) {
#pragma unroll
    for (int o = 16; o > 0; o >>= 1) v += __shfl_xor_sync(0xffffffffu, v, o);
    return v;
}
__device__ __forceinline__ void warp_sum2(float& a, float& b) {
#pragma unroll
    for (int o = 16; o > 0; o >>= 1) {
        a += __shfl_xor_sync(0xffffffffu, a, o);
        b += __shfl_xor_sync(0xffffffffu, b, o);
    }
}
// 4 independent chains interleaved: hides shfl latency across two rows
__device__ __forceinline__ void warp_sum4(float& a, float& b, float& c, float& d) {
#pragma unroll
    for (int o = 16; o > 0; o >>= 1) {
        a += __shfl_xor_sync(0xffffffffu, a, o);
        b += __shfl_xor_sync(0xffffffffu, b, o);
        c += __shfl_xor_sync(0xffffffffu, c, o);
        d += __shfl_xor_sync(0xffffffffu, d, o);
    }
}
__device__ __forceinline__ uint32_t smem_u32(const void* p) {
    uint32_t a;
    asm("{ .reg .u64 t; cvta.to.shared.u64 t, %1; cvt.u32.u64 %0, t; }"
        : "=r"(a) : "l"(p));
    return a;
}
__device__ __forceinline__ void cp16(uint32_t dst, const void* src) {
    asm volatile("cp.async.cg.shared.global [%0], [%1], 16;" :: "r"(dst), "l"(src));
}
__device__ __forceinline__ void cp_commit() {
    asm volatile("cp.async.commit_group;" ::: "memory");
}
template <int N> __device__ __forceinline__ void cp_wait() {
    asm volatile("cp.async.wait_group %0;" :: "n"(N) : "memory");
}

// ============================================================
// dual fp32 -> fp16 conversion (both weight matrices, one launch)
// ============================================================
__global__ void f2h_dual(const float* __restrict__ a, __half* __restrict__ oa, int na2,
                         const float* __restrict__ b, __half* __restrict__ ob, int nb2)
{
    int i = blockIdx.x * blockDim.x + threadIdx.x;
    if (i < na2) {
        float2 v = ((const float2*)a)[i];
        ((__half2*)oa)[i] = __floats2half2_rn(v.x, v.y);
    } else if (i - na2 < nb2) {
        int j = i - na2;
        float2 v = ((const float2*)b)[j];
        ((__half2*)ob)[j] = __floats2half2_rn(v.x, v.y);
    }
}

// ============================================================
// fp16 wmma GEMM (round-10 proven config, FROZEN):
// Tile 128x128, 256 threads, 8 warps (warp tile 64x32),
// K chunks of 32, 3-stage cp.async pipeline, 2 CTAs/SM.
// MODE 0: half-only Q/K/V out; MODE 1: fp32 out.
// ============================================================
#define KCH 32
#define KPAD 40
#define BUF_HALFS (128 * KPAD)
#define NSTAGE 3
#define GEMM_SMEM (NSTAGE * 2 * BUF_HALFS * 2)

template <int MODE>
__global__ __launch_bounds__(256, 2) void gemm_fp16(
    const __half* __restrict__ A, const __half* __restrict__ Bw,
    const float* __restrict__ bias0, const float* __restrict__ bias1,
    float* __restrict__ outp)
{
    extern __shared__ __half hsm[];
    __shared__ union {
        float bias2d[16][132];
        float stg[8][16 * 18];
    } u;

    int t = threadIdx.x;
    int w = t >> 5, lid = t & 31;
    int wy = w >> 2, wx = w & 3;
    int m0 = blockIdx.y * 128, n0 = blockIdx.x * 128;

    if (t < 128) {
        int col = n0 + t;
        float bv;
        if (MODE == 0) {
            int which = col / 768, c = col - which * 768;
            bv = (which == 0) ? bias0[c] : ((which == 2) ? bias1[c] : 0.f);
        } else bv = bias0[col];
#pragma unroll
        for (int r = 0; r < 16; r++) u.bias2d[r][t] = bv;
    }
    __syncthreads();

    wmma::fragment<wmma::accumulator, 16, 16, 16, float> acc[4][2];
#pragma unroll
    for (int i = 0; i < 4; i++)
#pragma unroll
        for (int j = 0; j < 2; j++)
            wmma::load_matrix_sync(acc[i][j], &u.bias2d[0][wx * 32 + j * 16], 132,
                                   wmma::mem_row_major);
    __syncthreads();

    const __half* gA = A + (size_t)m0 * 768;
    const __half* gB = Bw + (size_t)n0 * 768;

    auto stA = [&](int s) -> __half* { return hsm + s * 2 * BUF_HALFS; };
    auto stB = [&](int s) -> __half* { return hsm + s * 2 * BUF_HALFS + BUF_HALFS; };

    auto load_chunk = [&](int kc, int s) {
        uint32_t aS = smem_u32(stA(s));
        uint32_t bS = smem_u32(stB(s));
#pragma unroll
        for (int j = 0; j < 2; j++) {
            int idx = t + j * 256;
            int row = idx >> 2, c4 = idx & 3;
            cp16(aS + row * (KPAD * 2) + c4 * 16,
                 gA + (size_t)row * 768 + kc * KCH + c4 * 8);
            cp16(bS + row * (KPAD * 2) + c4 * 16,
                 gB + (size_t)row * 768 + kc * KCH + c4 * 8);
        }
        cp_commit();
    };

    const int NCHUNK = 24;
    load_chunk(0, 0);
    load_chunk(1, 1);
    for (int i = 0; i < NCHUNK; i++) {
        int s = i % NSTAGE;
        if (i + 2 < NCHUNK) { load_chunk(i + 2, (i + 2) % NSTAGE); cp_wait<2>(); }
        else if (i + 1 < NCHUNK) cp_wait<1>();
        else cp_wait<0>();
        __syncthreads();

        __half* As = stA(s);
        __half* Bs = stB(s);
#pragma unroll
        for (int kk = 0; kk < KCH; kk += 16) {
            wmma::fragment<wmma::matrix_a, 16, 16, 16, __half, wmma::row_major> af[4];
            wmma::fragment<wmma::matrix_b, 16, 16, 16, __half, wmma::col_major> bf[2];
#pragma unroll
            for (int q = 0; q < 4; q++)
                wmma::load_matrix_sync(af[q], &As[(wy * 64 + q * 16) * KPAD + kk], KPAD);
#pragma unroll
            for (int q = 0; q < 2; q++)
                wmma::load_matrix_sync(bf[q], &Bs[(wx * 32 + q * 16) * KPAD + kk], KPAD);
#pragma unroll
            for (int q = 0; q < 4; q++)
#pragma unroll
                for (int r = 0; r < 2; r++)
                    wmma::mma_sync(acc[q][r], af[q], bf[r], acc[q][r]);
        }
        __syncthreads();
    }

#pragma unroll
    for (int i = 0; i < 4; i++) {
        int row0 = m0 + wy * 64 + i * 16;
#pragma unroll
        for (int j = 0; j < 2; j++) {
            int col0 = n0 + wx * 32 + j * 16;
            if (MODE == 0) {
                int b = row0 >> 10, n = row0 & 1023;
                int which = col0 / 768;
                int c = col0 - which * 768;
                int h = c >> 6, d0 = c & 63;
                size_t off = ((size_t)(b * NHEAD + h) << 16) + (n << 6) + d0;
                __half* dsth = (which == 0 ? g_Qh : (which == 1 ? g_Kh : g_Vh)) + off;
                float* stw = &u.stg[w][0];
                wmma::store_matrix_sync(stw, acc[i][j], 18, wmma::mem_row_major);
                __syncwarp();
                int rr = lid >> 1, cc = (lid & 1) * 8;
                float* sp = stw + rr * 18 + cc;
                __half2 h0 = __floats2half2_rn(sp[0], sp[1]);
                __half2 h1 = __floats2half2_rn(sp[2], sp[3]);
                __half2 h2 = __floats2half2_rn(sp[4], sp[5]);
                __half2 h3 = __floats2half2_rn(sp[6], sp[7]);
                __half2* dp = (__half2*)(dsth + (size_t)rr * 64 + cc);
                dp[0] = h0; dp[1] = h1; dp[2] = h2; dp[3] = h3;
                __syncwarp();
            } else {
                wmma::store_matrix_sync(outp + (size_t)row0 * 768 + col0, acc[i][j],
                                        768, wmma::mem_row_major);
            }
        }
    }
}

// ============================================================
// learned LR + fused f2h(x). 512 blocks x 32 rows, paired reductions.
// ============================================================
__global__ __launch_bounds__(256) void lr_kernel2(
    const float* __restrict__ x, const float* __restrict__ lrw,
    const float* __restrict__ lrb, __half* __restrict__ Xh)
{
    __shared__ float ws[12 * 768];
    __shared__ float lb[12];
    int t = threadIdx.x, w = t >> 5, l = t & 31;
    for (int i = t; i < 12 * 768; i += 256) ws[i] = lrw[i];
    if (t < 12) lb[t] = lrb[t];
    __syncthreads();

    int rowbase = blockIdx.x * 32 + w * 4;
    for (int rr = 0; rr < 4; rr++) {
        int row = rowbase + rr;
        const float* xr = x + (size_t)row * 768;
        float xv[24];
#pragma unroll
        for (int k = 0; k < 24; k++) xv[k] = xr[l + k * 32];
        __half* xo = Xh + (size_t)row * 768;
#pragma unroll
        for (int k = 0; k < 24; k++) xo[l + k * 32] = __float2half(xv[k]);
        int b = row >> 10, n = row & 1023;
#pragma unroll
        for (int h = 0; h < 12; h += 2) {
            float s0 = 0.f, s1 = 0.f;
#pragma unroll
            for (int k = 0; k < 24; k++) {
                s0 = fmaf(xv[k], ws[h * 768 + l + k * 32], s0);
                s1 = fmaf(xv[k], ws[(h + 1) * 768 + l + k * 32], s1);
            }
            warp_sum2(s0, s1);
            if (l == 0) {
                float v0 = 1.f / (1.f + expf(-(s0 + lb[h])));
                float v1 = 1.f / (1.f + expf(-(s1 + lb[h + 1])));
                g_eta[(b * NHEAD + h) * 1024 + n]     = v0 * (1.f / 64.f);
                g_eta[(b * NHEAD + h + 1) * 1024 + n] = v1 * (1.f / 64.f);
            }
        }
    }
}

// ============================================================
// phase1 (tensor cores, 4-way split) + fused gradw partial.
// LN loop processes 2 rows/iteration with 4-way interleaved reductions.
// ============================================================
__global__ __launch_bounds__(256) void ttt_phase1_tc(
    const float* __restrict__ W1, const float* __restrict__ b1,
    const float* __restrict__ gamma, const float* __restrict__ beta)
{
    int bh = blockIdx.x >> 2, part = blockIdx.x & 3;
    int h = bh % NHEAD;
    __shared__ __half W1h[64 * 72];
    __shared__ float zs[8][16 * 68];
    __shared__ float b1s[64], gs[64], bs[64];
    __shared__ float gbacc[8 * 64];
    int t = threadIdx.x, w = t >> 5, l = t & 31;

    for (int i = t; i < 4096; i += 256) {
        int r = i >> 6, c = i & 63;
        W1h[r * 72 + c] = __float2half(W1[h * 4096 + i]);
    }
    if (t < 64) {
        b1s[t] = b1[h * 64 + t];
        gs[t]  = gamma[h * 64 + t];
        bs[t]  = beta[h * 64 + t];
    }
    __syncthreads();

    const __half* Kh = g_Kh + (size_t)bh * TOKHD;
    const __half* Vh = g_Vh + (size_t)bh * TOKHD;
    __half* Gh = g_Gh + (size_t)bh * TOKHD;
    const float* etap = g_eta + bh * 1024;

    float gb0 = 0.f, gb1 = 0.f;
    float g0 = gs[l], g1 = gs[l + 32];
    float bb0 = bs[l], bb1 = bs[l + 32];
    for (int s = 0; s < 2; s++) {
        int row0 = part * 256 + (s * 8 + w) * 16;
        wmma::fragment<wmma::accumulator, 16, 16, 16, float> acc[4];
#pragma unroll
        for (int n = 0; n < 4; n++) wmma::fill_fragment(acc[n], 0.f);
#pragma unroll
        for (int k = 0; k < 4; k++) {
            wmma::fragment<wmma::matrix_a, 16, 16, 16, __half, wmma::row_major> af;
            wmma::load_matrix_sync(af, Kh + (size_t)row0 * 64 + k * 16, 64);
#pragma unroll
            for (int n = 0; n < 4; n++) {
                wmma::fragment<wmma::matrix_b, 16, 16, 16, __half, wmma::row_major> bf;
                wmma::load_matrix_sync(bf, &W1h[(k * 16) * 72 + n * 16], 72);
                wmma::mma_sync(acc[n], af, bf, acc[n]);
            }
        }
#pragma unroll
        for (int n = 0; n < 4; n++)
            wmma::store_matrix_sync(&zs[w][n * 16], acc[n], 68, wmma::mem_row_major);
        __syncwarp();

#pragma unroll
        for (int r = 0; r < 16; r += 2) {
            int rowA = row0 + r, rowB = row0 + r + 1;
            float za0 = zs[w][r * 68 + l] + b1s[l];
            float za1 = zs[w][r * 68 + l + 32] + b1s[l + 32];
            float zb0 = zs[w][(r + 1) * 68 + l] + b1s[l];
            float zb1 = zs[w][(r + 1) * 68 + l + 32] + b1s[l + 32];
            float sa1 = za0 + za1, sa2 = za0 * za0 + za1 * za1;
            float sb1 = zb0 + zb1, sb2 = zb0 * zb0 + zb1 * zb1;
            warp_sum4(sa1, sa2, sb1, sb2);
            float muA = sa1 * (1.f / 64.f), muB = sb1 * (1.f / 64.f);
            float rstdA = rsqrtf(sa2 * (1.f / 64.f) - muA * muA + 1e-6f);
            float rstdB = rsqrtf(sb2 * (1.f / 64.f) - muB * muB + 1e-6f);
            float xa0 = (za0 - muA) * rstdA, xa1 = (za1 - muA) * rstdA;
            float xb0 = (zb0 - muB) * rstdB, xb1 = (zb1 - muB) * rstdB;
            float ka0 = __half2float(Kh[rowA * 64 + l]);
            float ka1 = __half2float(Kh[rowA * 64 + l + 32]);
            float va0 = __half2float(Vh[rowA * 64 + l]);
            float va1 = __half2float(Vh[rowA * 64 + l + 32]);
            float kb0 = __half2float(Kh[rowB * 64 + l]);
            float kb1 = __half2float(Kh[rowB * 64 + l + 32]);
            float vb0 = __half2float(Vh[rowB * 64 + l]);
            float vb1 = __half2float(Vh[rowB * 64 + l + 32]);
            float ga0 = (g0 * xa0 + bb0 - (va0 - ka0)) * g0;
            float ga1 = (g1 * xa1 + bb1 - (va1 - ka1)) * g1;
            float hb0 = (g0 * xb0 + bb0 - (vb0 - kb0)) * g0;
            float hb1 = (g1 * xb1 + bb1 - (vb1 - kb1)) * g1;
            float sgA = ga0 + ga1, sgxA = ga0 * xa0 + ga1 * xa1;
            float sgB = hb0 + hb1, sgxB = hb0 * xb0 + hb1 * xb1;
            warp_sum4(sgA, sgxA, sgB, sgxB);
            float scA = etap[rowA] * rstdA * (1.f / 64.f) * (1.f / 1024.f);
            float scB = etap[rowB] * rstdB * (1.f / 64.f) * (1.f / 1024.f);
            float fa0 = (64.f * ga0 - sgA - xa0 * sgxA) * scA;
            float fa1 = (64.f * ga1 - sgA - xa1 * sgxA) * scA;
            float fb0 = (64.f * hb0 - sgB - xb0 * sgxB) * scB;
            float fb1 = (64.f * hb1 - sgB - xb1 * sgxB) * scB;
            Gh[rowA * 64 + l]      = __float2half(fa0 * 1024.f);
            Gh[rowA * 64 + l + 32] = __float2half(fa1 * 1024.f);
            Gh[rowB * 64 + l]      = __float2half(fb0 * 1024.f);
            Gh[rowB * 64 + l + 32] = __float2half(fb1 * 1024.f);
            gb0 += fa0 + fb0; gb1 += fa1 + fb1;
        }
    }
    gbacc[w * 64 + l] = gb0;
    gbacc[w * 64 + l + 32] = gb1;
    __syncthreads();
    if (t < 64) {
        float s = 0.f;
#pragma unroll
        for (int ww = 0; ww < 8; ww++) s += gbacc[ww * 64 + t];
        g_b1part[(bh * 4 + part) * 64 + t] = s;
    }

    // fused gradw partial: XK[part]^T @ g[part]
    {
        const __half* Kp2 = Kh + part * 256 * 64;
        const __half* Gp2 = Gh + part * 256 * 64;
        int wt = w & 3, kh2 = w >> 2;
        wmma::fragment<wmma::accumulator, 16, 16, 16, float> acc2[4];
#pragma unroll
        for (int n = 0; n < 4; n++) wmma::fill_fragment(acc2[n], 0.f);
#pragma unroll
        for (int ks = 0; ks < 8; ks++) {
            int k = kh2 * 128 + ks * 16;
            wmma::fragment<wmma::matrix_a, 16, 16, 16, __half, wmma::col_major> af;
            wmma::load_matrix_sync(af, Kp2 + (size_t)k * 64 + wt * 16, 64);
#pragma unroll
            for (int n = 0; n < 4; n++) {
                wmma::fragment<wmma::matrix_b, 16, 16, 16, __half, wmma::row_major> bf;
                wmma::load_matrix_sync(bf, Gp2 + (size_t)k * 64 + n * 16, 64);
                wmma::mma_sync(acc2[n], af, bf, acc2[n]);
            }
        }
        __syncthreads();
#pragma unroll
        for (int n = 0; n < 4; n++)
            wmma::store_matrix_sync(&zs[w][n * 16], acc2[n], 68, wmma::mem_row_major);
        __syncthreads();

        float* dst = g_W1part + (size_t)(bh * 4 + part) * 4096;
        for (int i = t; i < 4096; i += 256) {
            int d = i >> 6, e = i & 63;
            int wt2 = d >> 4, r = d & 15;
            dst[i] = zs[wt2][r * 68 + e] + zs[wt2 + 4][r * 68 + e];
        }
    }
}

// ============================================================
// phase3 (tensor cores, 4-way split) with fused combine,
// LN loop processes 2 rows/iteration (paired 4-way reduction).
// ============================================================
__global__ __launch_bounds__(256) void ttt_phase3_tc(
    const float* __restrict__ W1, const float* __restrict__ b1,
    const float* __restrict__ gamma, const float* __restrict__ beta)
{
    int bh = blockIdx.x >> 2, part = blockIdx.x & 3;
    int h = bh % NHEAD, b = bh / NHEAD;
    __shared__ __half W1h[64 * 72];
    __shared__ float zs[8][16 * 68];
    __shared__ float b1s[64], gs[64], bs[64];
    int t = threadIdx.x, w = t >> 5, l = t & 31;

    {   // fused combine: fold 4 fp32 partials into half W1h
        const float* p0 = g_W1part + (size_t)(bh * 4 + 0) * 4096;
        const float* p1 = g_W1part + (size_t)(bh * 4 + 1) * 4096;
        const float* p2 = g_W1part + (size_t)(bh * 4 + 2) * 4096;
        const float* p3 = g_W1part + (size_t)(bh * 4 + 3) * 4096;
        for (int i = t; i < 4096; i += 256) {
            int r = i >> 6, c = i & 63;
            float s = p0[i] + p1[i] + p2[i] + p3[i];
            W1h[r * 72 + c] = __float2half(W1[h * 4096 + i] - s * (1.f / 1024.f));
        }
    }
    if (t < 64) {
        float s = g_b1part[(bh * 4 + 0) * 64 + t] + g_b1part[(bh * 4 + 1) * 64 + t]
                + g_b1part[(bh * 4 + 2) * 64 + t] + g_b1part[(bh * 4 + 3) * 64 + t];
        b1s[t] = b1[h * 64 + t] - s;
        gs[t]  = gamma[h * 64 + t];
        bs[t]  = beta[h * 64 + t];
    }
    __syncthreads();

    const __half* Qh = g_Qh + (size_t)bh * TOKHD;
    __half* Op = g_XQWh + (size_t)b * 1024 * CDIM;

    float g0 = gs[l], g1 = gs[l + 32];
    float bb0 = bs[l], bb1 = bs[l + 32];
    for (int s = 0; s < 2; s++) {
        int row0 = part * 256 + (s * 8 + w) * 16;
        wmma::fragment<wmma::accumulator, 16, 16, 16, float> acc[4];
#pragma unroll
        for (int n = 0; n < 4; n++) wmma::fill_fragment(acc[n], 0.f);
#pragma unroll
        for (int k = 0; k < 4; k++) {
            wmma::fragment<wmma::matrix_a, 16, 16, 16, __half, wmma::row_major> af;
            wmma::load_matrix_sync(af, Qh + (size_t)row0 * 64 + k * 16, 64);
#pragma unroll
            for (int n = 0; n < 4; n++) {
                wmma::fragment<wmma::matrix_b, 16, 16, 16, __half, wmma::row_major> bf;
                wmma::load_matrix_sync(bf, &W1h[(k * 16) * 72 + n * 16], 72);
                wmma::mma_sync(acc[n], af, bf, acc[n]);
            }
        }
#pragma unroll
        for (int n = 0; n < 4; n++)
            wmma::store_matrix_sync(&zs[w][n * 16], acc[n], 68, wmma::mem_row_major);
        __syncwarp();

#pragma unroll
        for (int r = 0; r < 16; r += 2) {
            int rowA = row0 + r, rowB = row0 + r + 1;
            float za0 = zs[w][r * 68 + l] + b1s[l];
            float za1 = zs[w][r * 68 + l + 32] + b1s[l + 32];
            float zb0 = zs[w][(r + 1) * 68 + l] + b1s[l];
            float zb1 = zs[w][(r + 1) * 68 + l + 32] + b1s[l + 32];
            float sa1 = za0 + za1, sa2 = za0 * za0 + za1 * za1;
            float sb1 = zb0 + zb1, sb2 = zb0 * zb0 + zb1 * zb1;
            warp_sum4(sa1, sa2, sb1, sb2);
            float muA = sa1 * (1.f / 64.f), muB = sb1 * (1.f / 64.f);
            float rstdA = rsqrtf(sa2 * (1.f / 64.f) - muA * muA + 1e-6f);
            float rstdB = rsqrtf(sb2 * (1.f / 64.f) - muB * muB + 1e-6f);
            float ya0 = g0 * ((za0 - muA) * rstdA) + bb0;
            float ya1 = g1 * ((za1 - muA) * rstdA) + bb1;
            float yb0 = g0 * ((zb0 - muB) * rstdB) + bb0;
            float yb1 = g1 * ((zb1 - muB) * rstdB) + bb1;
            float qa0 = __half2float(Qh[rowA * 64 + l]);
            float qa1 = __half2float(Qh[rowA * 64 + l + 32]);
            float qb0 = __half2float(Qh[rowB * 64 + l]);
            float qb1 = __half2float(Qh[rowB * 64 + l + 32]);
            Op[rowA * CDIM + h * 64 + l]      = __float2half(qa0 + ya0);
            Op[rowA * CDIM + h * 64 + l + 32] = __float2half(qa1 + ya1);
            Op[rowB * CDIM + h * 64 + l]      = __float2half(qb0 + yb0);
            Op[rowB * CDIM + h * 64 + l + 32] = __float2half(qb1 + yb1);
        }
    }
}

// ============================================================
extern "C" void kernel_launch(void* const* d_in, const int* in_sizes, int n_in,
                              void* d_out, int out_size)
{
    (void)in_sizes; (void)n_in; (void)out_size;
    const float* x     = (const float*)d_in[0];
    const float* qkvw  = (const float*)d_in[1];
    const float* qb    = (const float*)d_in[2];
    const float* vb    = (const float*)d_in[3];
    const float* pw    = (const float*)d_in[4];
    const float* pb    = (const float*)d_in[5];
    const float* lrw   = (const float*)d_in[6];
    const float* lrb   = (const float*)d_in[7];
    const float* gamma = (const float*)d_in[8];
    const float* beta  = (const float*)d_in[9];
    const float* W1    = (const float*)d_in[10];
    const float* b1    = (const float*)d_in[11];
    float* out = (float*)d_out;

    cudaFuncSetAttribute(gemm_fp16<0>, cudaFuncAttributeMaxDynamicSharedMemorySize, GEMM_SMEM);
    cudaFuncSetAttribute(gemm_fp16<1>, cudaFuncAttributeMaxDynamicSharedMemorySize, GEMM_SMEM);

    __half *Xh, *Wqh, *Wph, *XQWh;
    cudaGetSymbolAddress((void**)&Xh, g_Xh);
    cudaGetSymbolAddress((void**)&Wqh, g_Wqh);
    cudaGetSymbolAddress((void**)&Wph, g_Wph);
    cudaGetSymbolAddress((void**)&XQWh, g_XQWh);

    lr_kernel2<<<512, 256>>>(x, lrw, lrb, Xh);
    f2h_dual<<<(884736 + 294912 + 255) / 256, 256>>>(qkvw, Wqh, 884736,
                                                     pw, Wph, 294912);

    gemm_fp16<0><<<dim3(18, 128), 256, GEMM_SMEM>>>(Xh, Wqh, qb, vb, nullptr);

    ttt_phase1_tc<<<768, 256>>>(W1, b1, gamma, beta);
    ttt_phase3_tc<<<768, 256>>>(W1, b1, gamma, beta);

    gemm_fp16<1><<<dim3(6, 128), 256, GEMM_SMEM>>>(XQWh, Wph, pb, nullptr, out);
}

// round 15
// speedup vs baseline: 1.0521x; 1.0085x over previous
#include <cuda_runtime.h>
#include <cuda_fp16.h>
#include <mma.h>
#include <math.h>
#include <stdint.h>

using namespace nvcuda;

// Problem constants: B=16, N=1024, C=768, H=12, HD=64, one mini-batch (m=1024)
#define NTOK   16384
#define CDIM   768
#define NHEAD  12
#define HD     64
#define BH     192
#define TOKHD  65536          // 1024*64 per (b,h)

// ---- scratch (static device globals; no allocations anywhere) ----
__device__ float  g_eta[196608];     // [B,H,N]
__device__ float  g_b1part[49152];   // [BH,4,64] partial b1 grad sums
__device__ float  g_W1part[3145728]; // [BH,4,64,64] partial W1 grads
__device__ __half g_Xh[12582912];    // half(x) [16384,768]
__device__ __half g_Wqh[1769472];    // half(qkv_weight) [2304,768]
__device__ __half g_Wph[589824];     // half(proj_weight) [768,768]
__device__ __half g_XQWh[12582912];  // half pre-projection [B,N,C]
__device__ __half g_Qh[12582912];    // half Q [B,H,N,64]
__device__ __half g_Kh[12582912];    // half K
__device__ __half g_Vh[12582912];    // half V
__device__ __half g_Gh[12582912];    // half g scaled by 1024

__device__ __forceinline__ float warp_sum(float v) {
#pragma unroll
    for (int o = 16; o > 0; o >>= 1) v += __shfl_xor_sync(0xffffffffu, v, o);
    return v;
}
__device__ __forceinline__ void warp_sum2(float& a, float& b) {
#pragma unroll
    for (int o = 16; o > 0; o >>= 1) {
        a += __shfl_xor_sync(0xffffffffu, a, o);
        b += __shfl_xor_sync(0xffffffffu, b, o);
    }
}
__device__ __forceinline__ void warp_sum4(float& a, float& b, float& c, float& d) {
#pragma unroll
    for (int o = 16; o > 0; o >>= 1) {
        a += __shfl_xor_sync(0xffffffffu, a, o);
        b += __shfl_xor_sync(0xffffffffu, b, o);
        c += __shfl_xor_sync(0xffffffffu, c, o);
        d += __shfl_xor_sync(0xffffffffu, d, o);
    }
}
__device__ __forceinline__ uint32_t smem_u32(const void* p) {
    uint32_t a;
    asm("{ .reg .u64 t; cvta.to.shared.u64 t, %1; cvt.u32.u64 %0, t; }"
        : "=r"(a) : "l"(p));
    return a;
}
__device__ __forceinline__ void cp16(uint32_t dst, const void* src) {
    asm volatile("cp.async.cg.shared.global [%0], [%1], 16;" :: "r"(dst), "l"(src));
}
__device__ __forceinline__ void cp_commit() {
    asm volatile("cp.async.commit_group;" ::: "memory");
}
template <int N> __device__ __forceinline__ void cp_wait() {
    asm volatile("cp.async.wait_group %0;" :: "n"(N) : "memory");
}

// ============================================================
// dual fp32 -> fp16 conversion (both weight matrices, one launch)
// ============================================================
__global__ void f2h_dual(const float* __restrict__ a, __half* __restrict__ oa, int na2,
                         const float* __restrict__ b, __half* __restrict__ ob, int nb2)
{
    int i = blockIdx.x * blockDim.x + threadIdx.x;
    if (i < na2) {
        float2 v = ((const float2*)a)[i];
        ((__half2*)oa)[i] = __floats2half2_rn(v.x, v.y);
    } else if (i - na2 < nb2) {
        int j = i - na2;
        float2 v = ((const float2*)b)[j];
        ((__half2*)ob)[j] = __floats2half2_rn(v.x, v.y);
    }
}

// ============================================================
// fp16 wmma GEMM (round-10 proven config, FROZEN):
// Tile 128x128, 256 threads, 8 warps (warp tile 64x32),
// K chunks of 32, 3-stage cp.async pipeline, 2 CTAs/SM.
// MODE 0: half-only Q/K/V out; MODE 1: fp32 out.
// ============================================================
#define KCH 32
#define KPAD 40
#define BUF_HALFS (128 * KPAD)
#define NSTAGE 3
#define GEMM_SMEM (NSTAGE * 2 * BUF_HALFS * 2)

template <int MODE>
__global__ __launch_bounds__(256, 2) void gemm_fp16(
    const __half* __restrict__ A, const __half* __restrict__ Bw,
    const float* __restrict__ bias0, const float* __restrict__ bias1,
    float* __restrict__ outp)
{
    extern __shared__ __half hsm[];
    __shared__ union {
        float bias2d[16][132];
        float stg[8][16 * 18];
    } u;

    int t = threadIdx.x;
    int w = t >> 5, lid = t & 31;
    int wy = w >> 2, wx = w & 3;
    int m0 = blockIdx.y * 128, n0 = blockIdx.x * 128;

    if (t < 128) {
        int col = n0 + t;
        float bv;
        if (MODE == 0) {
            int which = col / 768, c = col - which * 768;
            bv = (which == 0) ? bias0[c] : ((which == 2) ? bias1[c] : 0.f);
        } else bv = bias0[col];
#pragma unroll
        for (int r = 0; r < 16; r++) u.bias2d[r][t] = bv;
    }
    __syncthreads();

    wmma::fragment<wmma::accumulator, 16, 16, 16, float> acc[4][2];
#pragma unroll
    for (int i = 0; i < 4; i++)
#pragma unroll
        for (int j = 0; j < 2; j++)
            wmma::load_matrix_sync(acc[i][j], &u.bias2d[0][wx * 32 + j * 16], 132,
                                   wmma::mem_row_major);
    __syncthreads();

    const __half* gA = A + (size_t)m0 * 768;
    const __half* gB = Bw + (size_t)n0 * 768;

    auto stA = [&](int s) -> __half* { return hsm + s * 2 * BUF_HALFS; };
    auto stB = [&](int s) -> __half* { return hsm + s * 2 * BUF_HALFS + BUF_HALFS; };

    auto load_chunk = [&](int kc, int s) {
        uint32_t aS = smem_u32(stA(s));
        uint32_t bS = smem_u32(stB(s));
#pragma unroll
        for (int j = 0; j < 2; j++) {
            int idx = t + j * 256;
            int row = idx >> 2, c4 = idx & 3;
            cp16(aS + row * (KPAD * 2) + c4 * 16,
                 gA + (size_t)row * 768 + kc * KCH + c4 * 8);
            cp16(bS + row * (KPAD * 2) + c4 * 16,
                 gB + (size_t)row * 768 + kc * KCH + c4 * 8);
        }
        cp_commit();
    };

    const int NCHUNK = 24;
    load_chunk(0, 0);
    load_chunk(1, 1);
    for (int i = 0; i < NCHUNK; i++) {
        int s = i % NSTAGE;
        if (i + 2 < NCHUNK) { load_chunk(i + 2, (i + 2) % NSTAGE); cp_wait<2>(); }
        else if (i + 1 < NCHUNK) cp_wait<1>();
        else cp_wait<0>();
        __syncthreads();

        __half* As = stA(s);
        __half* Bs = stB(s);
#pragma unroll
        for (int kk = 0; kk < KCH; kk += 16) {
            wmma::fragment<wmma::matrix_a, 16, 16, 16, __half, wmma::row_major> af[4];
            wmma::fragment<wmma::matrix_b, 16, 16, 16, __half, wmma::col_major> bf[2];
#pragma unroll
            for (int q = 0; q < 4; q++)
                wmma::load_matrix_sync(af[q], &As[(wy * 64 + q * 16) * KPAD + kk], KPAD);
#pragma unroll
            for (int q = 0; q < 2; q++)
                wmma::load_matrix_sync(bf[q], &Bs[(wx * 32 + q * 16) * KPAD + kk], KPAD);
#pragma unroll
            for (int q = 0; q < 4; q++)
#pragma unroll
                for (int r = 0; r < 2; r++)
                    wmma::mma_sync(acc[q][r], af[q], bf[r], acc[q][r]);
        }
        __syncthreads();
    }

#pragma unroll
    for (int i = 0; i < 4; i++) {
        int row0 = m0 + wy * 64 + i * 16;
#pragma unroll
        for (int j = 0; j < 2; j++) {
            int col0 = n0 + wx * 32 + j * 16;
            if (MODE == 0) {
                int b = row0 >> 10, n = row0 & 1023;
                int which = col0 / 768;
                int c = col0 - which * 768;
                int h = c >> 6, d0 = c & 63;
                size_t off = ((size_t)(b * NHEAD + h) << 16) + (n << 6) + d0;
                __half* dsth = (which == 0 ? g_Qh : (which == 1 ? g_Kh : g_Vh)) + off;
                float* stw = &u.stg[w][0];
                wmma::store_matrix_sync(stw, acc[i][j], 18, wmma::mem_row_major);
                __syncwarp();
                int rr = lid >> 1, cc = (lid & 1) * 8;
                float* sp = stw + rr * 18 + cc;
                __half2 h0 = __floats2half2_rn(sp[0], sp[1]);
                __half2 h1 = __floats2half2_rn(sp[2], sp[3]);
                __half2 h2 = __floats2half2_rn(sp[4], sp[5]);
                __half2 h3 = __floats2half2_rn(sp[6], sp[7]);
                __half2* dp = (__half2*)(dsth + (size_t)rr * 64 + cc);
                dp[0] = h0; dp[1] = h1; dp[2] = h2; dp[3] = h3;
                __syncwarp();
            } else {
                wmma::store_matrix_sync(outp + (size_t)row0 * 768 + col0, acc[i][j],
                                        768, wmma::mem_row_major);
            }
        }
    }
}

// ============================================================
// learned LR + fused f2h(x). 512 blocks x 32 rows, paired reductions.
// ============================================================
__global__ __launch_bounds__(256) void lr_kernel2(
    const float* __restrict__ x, const float* __restrict__ lrw,
    const float* __restrict__ lrb, __half* __restrict__ Xh)
{
    __shared__ float ws[12 * 768];
    __shared__ float lb[12];
    int t = threadIdx.x, w = t >> 5, l = t & 31;
    for (int i = t; i < 12 * 768; i += 256) ws[i] = lrw[i];
    if (t < 12) lb[t] = lrb[t];
    __syncthreads();

    int rowbase = blockIdx.x * 32 + w * 4;
    for (int rr = 0; rr < 4; rr++) {
        int row = rowbase + rr;
        const float* xr = x + (size_t)row * 768;
        float xv[24];
#pragma unroll
        for (int k = 0; k < 24; k++) xv[k] = xr[l + k * 32];
        __half* xo = Xh + (size_t)row * 768;
#pragma unroll
        for (int k = 0; k < 24; k++) xo[l + k * 32] = __float2half(xv[k]);
        int b = row >> 10, n = row & 1023;
#pragma unroll
        for (int h = 0; h < 12; h += 2) {
            float s0 = 0.f, s1 = 0.f;
#pragma unroll
            for (int k = 0; k < 24; k++) {
                s0 = fmaf(xv[k], ws[h * 768 + l + k * 32], s0);
                s1 = fmaf(xv[k], ws[(h + 1) * 768 + l + k * 32], s1);
            }
            warp_sum2(s0, s1);
            if (l == 0) {
                float v0 = 1.f / (1.f + expf(-(s0 + lb[h])));
                float v1 = 1.f / (1.f + expf(-(s1 + lb[h + 1])));
                g_eta[(b * NHEAD + h) * 1024 + n]     = v0 * (1.f / 64.f);
                g_eta[(b * NHEAD + h + 1) * 1024 + n] = v1 * (1.f / 64.f);
            }
        }
    }
}

// ============================================================
// phase1 (tensor cores, 4-way split) + fused gradw partial.
// LN loop: lane l owns contiguous dims (2l, 2l+1) -> vectorized
// float2/half2 accesses; 2 rows/iter, 4-way interleaved reductions.
// ============================================================
__global__ __launch_bounds__(256) void ttt_phase1_tc(
    const float* __restrict__ W1, const float* __restrict__ b1,
    const float* __restrict__ gamma, const float* __restrict__ beta)
{
    int bh = blockIdx.x >> 2, part = blockIdx.x & 3;
    int h = bh % NHEAD;
    __shared__ __half W1h[64 * 72];
    __shared__ float zs[8][16 * 68];
    __shared__ float b1s[64], gs[64], bs[64];
    __shared__ float gbacc[8 * 64];
    int t = threadIdx.x, w = t >> 5, l = t & 31;

    for (int i = t; i < 4096; i += 256) {
        int r = i >> 6, c = i & 63;
        W1h[r * 72 + c] = __float2half(W1[h * 4096 + i]);
    }
    if (t < 64) {
        b1s[t] = b1[h * 64 + t];
        gs[t]  = gamma[h * 64 + t];
        bs[t]  = beta[h * 64 + t];
    }
    __syncthreads();

    const __half2* Kh2 = (const __half2*)(g_Kh + (size_t)bh * TOKHD);
    const __half2* Vh2 = (const __half2*)(g_Vh + (size_t)bh * TOKHD);
    __half2* Gh2 = (__half2*)(g_Gh + (size_t)bh * TOKHD);
    const __half* Kh = g_Kh + (size_t)bh * TOKHD;
    __half* Gh = g_Gh + (size_t)bh * TOKHD;
    const float* etap = g_eta + bh * 1024;

    int d2 = 2 * l;                  // lane owns dims d2, d2+1
    float b1a = b1s[d2], b1b = b1s[d2 + 1];
    float g0 = gs[d2], g1 = gs[d2 + 1];
    float bb0 = bs[d2], bb1 = bs[d2 + 1];

    float gb0 = 0.f, gb1 = 0.f;
    for (int s = 0; s < 2; s++) {
        int row0 = part * 256 + (s * 8 + w) * 16;
        wmma::fragment<wmma::accumulator, 16, 16, 16, float> acc[4];
#pragma unroll
        for (int n = 0; n < 4; n++) wmma::fill_fragment(acc[n], 0.f);
#pragma unroll
        for (int k = 0; k < 4; k++) {
            wmma::fragment<wmma::matrix_a, 16, 16, 16, __half, wmma::row_major> af;
            wmma::load_matrix_sync(af, Kh + (size_t)row0 * 64 + k * 16, 64);
#pragma unroll
            for (int n = 0; n < 4; n++) {
                wmma::fragment<wmma::matrix_b, 16, 16, 16, __half, wmma::row_major> bf;
                wmma::load_matrix_sync(bf, &W1h[(k * 16) * 72 + n * 16], 72);
                wmma::mma_sync(acc[n], af, bf, acc[n]);
            }
        }
#pragma unroll
        for (int n = 0; n < 4; n++)
            wmma::store_matrix_sync(&zs[w][n * 16], acc[n], 68, wmma::mem_row_major);
        __syncwarp();

#pragma unroll
        for (int r = 0; r < 16; r += 2) {
            int rowA = row0 + r, rowB = row0 + r + 1;
            float2 zA = *(const float2*)&zs[w][r * 68 + d2];
            float2 zB = *(const float2*)&zs[w][(r + 1) * 68 + d2];
            float za0 = zA.x + b1a, za1 = zA.y + b1b;
            float zb0 = zB.x + b1a, zb1 = zB.y + b1b;
            float sa1 = za0 + za1, sa2 = za0 * za0 + za1 * za1;
            float sb1 = zb0 + zb1, sb2 = zb0 * zb0 + zb1 * zb1;
            warp_sum4(sa1, sa2, sb1, sb2);
            float muA = sa1 * (1.f / 64.f), muB = sb1 * (1.f / 64.f);
            float rstdA = rsqrtf(sa2 * (1.f / 64.f) - muA * muA + 1e-6f);
            float rstdB = rsqrtf(sb2 * (1.f / 64.f) - muB * muB + 1e-6f);
            float xa0 = (za0 - muA) * rstdA, xa1 = (za1 - muA) * rstdA;
            float xb0 = (zb0 - muB) * rstdB, xb1 = (zb1 - muB) * rstdB;
            float2 kA = __half22float2(Kh2[rowA * 32 + l]);
            float2 vA = __half22float2(Vh2[rowA * 32 + l]);
            float2 kB = __half22float2(Kh2[rowB * 32 + l]);
            float2 vB = __half22float2(Vh2[rowB * 32 + l]);
            float ga0 = (g0 * xa0 + bb0 - (vA.x - kA.x)) * g0;
            float ga1 = (g1 * xa1 + bb1 - (vA.y - kA.y)) * g1;
            float hb0 = (g0 * xb0 + bb0 - (vB.x - kB.x)) * g0;
            float hb1 = (g1 * xb1 + bb1 - (vB.y - kB.y)) * g1;
            float sgA = ga0 + ga1, sgxA = ga0 * xa0 + ga1 * xa1;
            float sgB = hb0 + hb1, sgxB = hb0 * xb0 + hb1 * xb1;
            warp_sum4(sgA, sgxA, sgB, sgxB);
            float scA = etap[rowA] * rstdA * (1.f / 64.f);
            float scB = etap[rowB] * rstdB * (1.f / 64.f);
            // note: store g*1024, and g itself has the 1/1024; combined: just sc (no /1024, no *1024)
            float fa0 = (64.f * ga0 - sgA - xa0 * sgxA) * scA;
            float fa1 = (64.f * ga1 - sgA - xa1 * sgxA) * scA;
            float fb0 = (64.f * hb0 - sgB - xb0 * sgxB) * scB;
            float fb1 = (64.f * hb1 - sgB - xb1 * sgxB) * scB;
            Gh2[rowA * 32 + l] = __floats2half2_rn(fa0, fa1);
            Gh2[rowB * 32 + l] = __floats2half2_rn(fb0, fb1);
            // b1 partial accumulates the true (unscaled) g: f / 1024
            gb0 += (fa0 + fb0) * (1.f / 1024.f);
            gb1 += (fa1 + fb1) * (1.f / 1024.f);
        }
    }
    gbacc[w * 64 + d2] = gb0;
    gbacc[w * 64 + d2 + 1] = gb1;
    __syncthreads();
    if (t < 64) {
        float s = 0.f;
#pragma unroll
        for (int ww = 0; ww < 8; ww++) s += gbacc[ww * 64 + t];
        g_b1part[(bh * 4 + part) * 64 + t] = s;
    }

    // fused gradw partial: XK[part]^T @ g[part]
    {
        const __half* Kp2 = Kh + part * 256 * 64;
        const __half* Gp2 = Gh + part * 256 * 64;
        int wt = w & 3, kh2 = w >> 2;
        wmma::fragment<wmma::accumulator, 16, 16, 16, float> acc2[4];
#pragma unroll
        for (int n = 0; n < 4; n++) wmma::fill_fragment(acc2[n], 0.f);
#pragma unroll
        for (int ks = 0; ks < 8; ks++) {
            int k = kh2 * 128 + ks * 16;
            wmma::fragment<wmma::matrix_a, 16, 16, 16, __half, wmma::col_major> af;
            wmma::load_matrix_sync(af, Kp2 + (size_t)k * 64 + wt * 16, 64);
#pragma unroll
            for (int n = 0; n < 4; n++) {
                wmma::fragment<wmma::matrix_b, 16, 16, 16, __half, wmma::row_major> bf;
                wmma::load_matrix_sync(bf, Gp2 + (size_t)k * 64 + n * 16, 64);
                wmma::mma_sync(acc2[n], af, bf, acc2[n]);
            }
        }
        __syncthreads();
#pragma unroll
        for (int n = 0; n < 4; n++)
            wmma::store_matrix_sync(&zs[w][n * 16], acc2[n], 68, wmma::mem_row_major);
        __syncthreads();

        float* dst = g_W1part + (size_t)(bh * 4 + part) * 4096;
        for (int i = t; i < 4096; i += 256) {
            int d = i >> 6, e = i & 63;
            int wt2 = d >> 4, r = d & 15;
            dst[i] = zs[wt2][r * 68 + e] + zs[wt2 + 4][r * 68 + e];
        }
    }
}

// ============================================================
// phase3 (tensor cores, 4-way split) with fused combine,
// vectorized LN loop (2 rows/iter, lanes own contiguous dim pairs).
// ============================================================
__global__ __launch_bounds__(256) void ttt_phase3_tc(
    const float* __restrict__ W1, const float* __restrict__ b1,
    const float* __restrict__ gamma, const float* __restrict__ beta)
{
    int bh = blockIdx.x >> 2, part = blockIdx.x & 3;
    int h = bh % NHEAD, b = bh / NHEAD;
    __shared__ __half W1h[64 * 72];
    __shared__ float zs[8][16 * 68];
    __shared__ float b1s[64], gs[64], bs[64];
    int t = threadIdx.x, w = t >> 5, l = t & 31;

    {   // fused combine: fold 4 fp32 partials into half W1h
        const float* p0 = g_W1part + (size_t)(bh * 4 + 0) * 4096;
        const float* p1 = g_W1part + (size_t)(bh * 4 + 1) * 4096;
        const float* p2 = g_W1part + (size_t)(bh * 4 + 2) * 4096;
        const float* p3 = g_W1part + (size_t)(bh * 4 + 3) * 4096;
        for (int i = t; i < 4096; i += 256) {
            int r = i >> 6, c = i & 63;
            float s = p0[i] + p1[i] + p2[i] + p3[i];
            W1h[r * 72 + c] = __float2half(W1[h * 4096 + i] - s * (1.f / 1024.f));
        }
    }
    if (t < 64) {
        float s = g_b1part[(bh * 4 + 0) * 64 + t] + g_b1part[(bh * 4 + 1) * 64 + t]
                + g_b1part[(bh * 4 + 2) * 64 + t] + g_b1part[(bh * 4 + 3) * 64 + t];
        b1s[t] = b1[h * 64 + t] - s;
        gs[t]  = gamma[h * 64 + t];
        bs[t]  = beta[h * 64 + t];
    }
    __syncthreads();

    const __half2* Qh2 = (const __half2*)(g_Qh + (size_t)bh * TOKHD);
    const __half* Qh = g_Qh + (size_t)bh * TOKHD;
    __half* Op = g_XQWh + (size_t)b * 1024 * CDIM;

    int d2 = 2 * l;
    float b1a = b1s[d2], b1b = b1s[d2 + 1];
    float g0 = gs[d2], g1 = gs[d2 + 1];
    float bb0 = bs[d2], bb1 = bs[d2 + 1];

    for (int s = 0; s < 2; s++) {
        int row0 = part * 256 + (s * 8 + w) * 16;
        wmma::fragment<wmma::accumulator, 16, 16, 16, float> acc[4];
#pragma unroll
        for (int n = 0; n < 4; n++) wmma::fill_fragment(acc[n], 0.f);
#pragma unroll
        for (int k = 0; k < 4; k++) {
            wmma::fragment<wmma::matrix_a, 16, 16, 16, __half, wmma::row_major> af;
            wmma::load_matrix_sync(af, Qh + (size_t)row0 * 64 + k * 16, 64);
#pragma unroll
            for (int n = 0; n < 4; n++) {
                wmma::fragment<wmma::matrix_b, 16, 16, 16, __half, wmma::row_major> bf;
                wmma::load_matrix_sync(bf, &W1h[(k * 16) * 72 + n * 16], 72);
                wmma::mma_sync(acc[n], af, bf, acc[n]);
            }
        }
#pragma unroll
        for (int n = 0; n < 4; n++)
            wmma::store_matrix_sync(&zs[w][n * 16], acc[n], 68, wmma::mem_row_major);
        __syncwarp();

#pragma unroll
        for (int r = 0; r < 16; r += 2) {
            int rowA = row0 + r, rowB = row0 + r + 1;
            float2 zA = *(const float2*)&zs[w][r * 68 + d2];
            float2 zB = *(const float2*)&zs[w][(r + 1) * 68 + d2];
            float za0 = zA.x + b1a, za1 = zA.y + b1b;
            float zb0 = zB.x + b1a, zb1 = zB.y + b1b;
            float sa1 = za0 + za1, sa2 = za0 * za0 + za1 * za1;
            float sb1 = zb0 + zb1, sb2 = zb0 * zb0 + zb1 * zb1;
            warp_sum4(sa1, sa2, sb1, sb2);
            float muA = sa1 * (1.f / 64.f), muB = sb1 * (1.f / 64.f);
            float rstdA = rsqrtf(sa2 * (1.f / 64.f) - muA * muA + 1e-6f);
            float rstdB = rsqrtf(sb2 * (1.f / 64.f) - muB * muB + 1e-6f);
            float ya0 = g0 * ((za0 - muA) * rstdA) + bb0;
            float ya1 = g1 * ((za1 - muA) * rstdA) + bb1;
            float yb0 = g0 * ((zb0 - muB) * rstdB) + bb0;
            float yb1 = g1 * ((zb1 - muB) * rstdB) + bb1;
            float2 qA = __half22float2(Qh2[rowA * 32 + l]);
            float2 qB = __half22float2(Qh2[rowB * 32 + l]);
            *(__half2*)&Op[rowA * CDIM + h * 64 + d2] =
                __floats2half2_rn(qA.x + ya0, qA.y + ya1);
            *(__half2*)&Op[rowB * CDIM + h * 64 + d2] =
                __floats2half2_rn(qB.x + yb0, qB.y + yb1);
        }
    }
}

// ============================================================
extern "C" void kernel_launch(void* const* d_in, const int* in_sizes, int n_in,
                              void* d_out, int out_size)
{
    (void)in_sizes; (void)n_in; (void)out_size;
    const float* x     = (const float*)d_in[0];
    const float* qkvw  = (const float*)d_in[1];
    const float* qb    = (const float*)d_in[2];
    const float* vb    = (const float*)d_in[3];
    const float* pw    = (const float*)d_in[4];
    const float* pb    = (const float*)d_in[5];
    const float* lrw   = (const float*)d_in[6];
    const float* lrb   = (const float*)d_in[7];
    const float* gamma = (const float*)d_in[8];
    const float* beta  = (const float*)d_in[9];
    const float* W1    = (const float*)d_in[10];
    const float* b1    = (const float*)d_in[11];
    float* out = (float*)d_out;

    cudaFuncSetAttribute(gemm_fp16<0>, cudaFuncAttributeMaxDynamicSharedMemorySize, GEMM_SMEM);
    cudaFuncSetAttribute(gemm_fp16<1>, cudaFuncAttributeMaxDynamicSharedMemorySize, GEMM_SMEM);

    __half *Xh, *Wqh, *Wph, *XQWh;
    cudaGetSymbolAddress((void**)&Xh, g_Xh);
    cudaGetSymbolAddress((void**)&Wqh, g_Wqh);
    cudaGetSymbolAddress((void**)&Wph, g_Wph);
    cudaGetSymbolAddress((void**)&XQWh, g_XQWh);

    lr_kernel2<<<512, 256>>>(x, lrw, lrb, Xh);
    f2h_dual<<<(884736 + 294912 + 255) / 256, 256>>>(qkvw, Wqh, 884736,
                                                     pw, Wph, 294912);

    gemm_fp16<0><<<dim3(18, 128), 256, GEMM_SMEM>>>(Xh, Wqh, qb, vb, nullptr);

    ttt_phase1_tc<<<768, 256>>>(W1, b1, gamma, beta);
    ttt_phase3_tc<<<768, 256>>>(W1, b1, gamma, beta);

    gemm_fp16<1><<<dim3(6, 128), 256, GEMM_SMEM>>>(XQWh, Wph, pb, nullptr, out);
}